// round 6
// baseline (speedup 1.0000x reference)
#include <cuda_runtime.h>
#include <cstdint>
#include <cstddef>

// Problem constants (fixed by setup_inputs)
#define NN 4
#define H0 60
#define W0 80
#define H1 60
#define W1 80
#define LL (H0*W0)     // 4800 rows
#define SS (H1*W1)     // 4800 cols
#define NL (NN*LL)
#define THRV 0.2f
#define BR 2

#define TPB 512
#define NW (TPB/32)        // 16 warps
#define NQ (SS/4)          // 1200 float4 per row
#define ROWB (SS*4)        // 19200 bytes per row
#define RPS 2              // rows per pipeline stage
#define STAGEB (RPS*ROWB)  // 38400
#define DEPTH 5            // pipeline stages (10 rows in flight)
#define CTAS_PER_N 37      // 37*4 = 148 CTAs = 1 per SM
#define MAXROWS 130        // ceil(4800/37)
#define TAILQ (NQ - 2*TPB) // 176: threads with a 3rd float4

// smem layout (dynamic)
#define SM_TILES 0                          // DEPTH*STAGEB = 192000
#define SM_PMAX  (DEPTH*STAGEB)             // 192000
#define SM_PCNT  (SM_PMAX + MAXROWS*NW*4)   // 200320
#define SM_PIDX  (SM_PCNT + MAXROWS*NW*4)   // 208640
#define SM_MBAR  (SM_PIDX + MAXROWS*NW*4)   // 216960
#define SMEM_REQ 217088

// Scratch (no allocations allowed). g_colmax zero at entry: module zero-init on
// first call, cleanup_kernel restores it at the end of every call.
__device__ unsigned g_colmax[NN*SS];     // colmax as u32 bit pattern (nonneg floats)
__device__ float    g_rowmax[NL];
__device__ int      g_rowj[NL];          // min index achieving rowmax
__device__ int      g_rowcnt[NL];        // count of elements == rowmax

__global__ void cleanup_kernel() {
    int i = blockIdx.x * blockDim.x + threadIdx.x;
    if (i < NN*SS) g_colmax[i] = 0u;
}

__device__ __forceinline__ uint32_t smem_u32(const void* p) {
    uint32_t a;
    asm("{ .reg .u64 t; cvta.to.shared.u64 t, %1; cvt.u32.u64 %0, t; }" : "=r"(a) : "l"(p));
    return a;
}
__device__ __forceinline__ void mbar_init(uint32_t m, uint32_t cnt) {
    asm volatile("mbarrier.init.shared.b64 [%0], %1;" :: "r"(m), "r"(cnt) : "memory");
}
__device__ __forceinline__ void mbar_expect_tx(uint32_t m, uint32_t bytes) {
    asm volatile("mbarrier.arrive.expect_tx.shared.b64 _, [%0], %1;" :: "r"(m), "r"(bytes) : "memory");
}
__device__ __forceinline__ void bulk_ldg(uint32_t dst, const void* src, uint32_t bytes, uint32_t mbar) {
    asm volatile("cp.async.bulk.shared::cluster.global.mbarrier::complete_tx::bytes [%0], [%1], %2, [%3];"
                 :: "r"(dst), "l"(src), "r"(bytes), "r"(mbar) : "memory");
}
__device__ __forceinline__ void mbar_wait(uint32_t m, uint32_t ph) {
    uint32_t done;
    asm volatile("{\n\t.reg .pred p;\n\t"
                 "mbarrier.try_wait.parity.acquire.cta.shared::cta.b64 p, [%1], %2;\n\t"
                 "selp.b32 %0, 1, 0, p;\n\t}"
                 : "=r"(done) : "r"(m), "r"(ph) : "memory");
    if (!done) {
        asm volatile("{\n\t.reg .pred P1;\n\t"
                     "W_%=:\n\t"
                     "mbarrier.try_wait.parity.acquire.cta.shared::cta.b64 P1, [%0], %1, 0x989680;\n\t"
                     "@P1 bra.uni D_%=;\n\t"
                     "bra.uni W_%=;\n\t"
                     "D_%=:\n\t}"
                     :: "r"(m), "r"(ph) : "memory");
    }
}

__global__ __launch_bounds__(TPB) void pass1(const float* __restrict__ conf) {
    extern __shared__ __align__(16) unsigned char smem[];
    const int b = blockIdx.x;          // 0..36
    const int n = blockIdx.y;          // 0..3
    const int t = threadIdx.x;
    const int warp = t >> 5, lane = t & 31;
    const bool tail = t < TAILQ;       // t < 176

    const int rstart = (b * 4800) / CTAS_PER_N;
    const int rend   = ((b + 1) * 4800) / CTAS_PER_N;
    const int nrows  = rend - rstart;     // 129 or 130
    const int nstages = (nrows + RPS - 1) / RPS;
    const size_t grow0 = (size_t)n * LL + rstart;

    float4* tiles = (float4*)(smem + SM_TILES);
    float*  spmax = (float*)(smem + SM_PMAX);
    int*    spcnt = (int*)(smem + SM_PCNT);
    int*    spidx = (int*)(smem + SM_PIDX);
    const uint32_t sbase = smem_u32(smem);
    const uint32_t mb0   = sbase + SM_MBAR;

    // init pipeline
    if (t == 0) {
        for (int s = 0; s < DEPTH; s++) mbar_init(mb0 + 8*s, 1);
        asm volatile("fence.proxy.async.shared::cta;" ::: "memory");
    }
    __syncthreads();
    if (t == 0) {
        // stage s covers rows [s*RPS, s*RPS+1]; always load full 2 rows (an odd-nrows
        // CTA reads 1 unused in-bounds row; the global-last CTA has even nrows).
        for (int s = 0; s < DEPTH; s++) {
            mbar_expect_tx(mb0 + 8*s, STAGEB);
            bulk_ldg(sbase + s*STAGEB, (const char*)conf + (grow0 + s*RPS) * ROWB, STAGEB, mb0 + 8*s);
        }
    }

    // colmax accumulators in integer domain (umax == fmax for nonneg floats)
    uint4 c0 = {0,0,0,0}, c1 = {0,0,0,0}, c2 = {0,0,0,0};

    int stage = 0, ph = 0;
    for (int s = 0; s < nstages; s++) {
        mbar_wait(mb0 + 8*stage, ph);

#pragma unroll
        for (int rr = 0; rr < RPS; rr++) {
            const int r = s * RPS + rr;
            if (r >= nrows) break;

            const float4* tp = tiles + (stage * RPS + rr) * NQ + t;
            float4 a0 = tp[0];
            float4 a1 = tp[TPB];
            float4 a2 = tail ? tp[2*TPB] : make_float4(0.f,0.f,0.f,0.f);

            c0.x = umax(c0.x, __float_as_uint(a0.x)); c0.y = umax(c0.y, __float_as_uint(a0.y));
            c0.z = umax(c0.z, __float_as_uint(a0.z)); c0.w = umax(c0.w, __float_as_uint(a0.w));
            c1.x = umax(c1.x, __float_as_uint(a1.x)); c1.y = umax(c1.y, __float_as_uint(a1.y));
            c1.z = umax(c1.z, __float_as_uint(a1.z)); c1.w = umax(c1.w, __float_as_uint(a1.w));
            c2.x = umax(c2.x, __float_as_uint(a2.x)); c2.y = umax(c2.y, __float_as_uint(a2.y));
            c2.z = umax(c2.z, __float_as_uint(a2.z)); c2.w = umax(c2.w, __float_as_uint(a2.w));

            float4 rm;
            rm.x = fmaxf(fmaxf(a0.x, a1.x), a2.x);
            rm.y = fmaxf(fmaxf(a0.y, a1.y), a2.y);
            rm.z = fmaxf(fmaxf(a0.z, a1.z), a2.z);
            rm.w = fmaxf(fmaxf(a0.w, a1.w), a2.w);
            float tm = fmaxf(fmaxf(rm.x, rm.y), fmaxf(rm.z, rm.w));

            float wm = __uint_as_float(__reduce_max_sync(0xffffffffu, __float_as_uint(tm)));

            unsigned lcnt = 0u, lidx = 0x7fffffffu;
            if (tm == wm) {
                int j0 = t * 4;
                if (a0.x == wm) { lcnt++; lidx = min(lidx, (unsigned)(j0)); }
                if (a0.y == wm) { lcnt++; lidx = min(lidx, (unsigned)(j0+1)); }
                if (a0.z == wm) { lcnt++; lidx = min(lidx, (unsigned)(j0+2)); }
                if (a0.w == wm) { lcnt++; lidx = min(lidx, (unsigned)(j0+3)); }
                int j1 = (t + TPB) * 4;
                if (a1.x == wm) { lcnt++; lidx = min(lidx, (unsigned)(j1)); }
                if (a1.y == wm) { lcnt++; lidx = min(lidx, (unsigned)(j1+1)); }
                if (a1.z == wm) { lcnt++; lidx = min(lidx, (unsigned)(j1+2)); }
                if (a1.w == wm) { lcnt++; lidx = min(lidx, (unsigned)(j1+3)); }
                int j2 = (t + 2*TPB) * 4;
                if (a2.x == wm) { lcnt++; lidx = min(lidx, (unsigned)(j2)); }
                if (a2.y == wm) { lcnt++; lidx = min(lidx, (unsigned)(j2+1)); }
                if (a2.z == wm) { lcnt++; lidx = min(lidx, (unsigned)(j2+2)); }
                if (a2.w == wm) { lcnt++; lidx = min(lidx, (unsigned)(j2+3)); }
            }
            unsigned wcnt = __reduce_add_sync(0xffffffffu, lcnt);
            unsigned widx = __reduce_min_sync(0xffffffffu, lidx);
            if (lane == 0) {
                spmax[r*NW + warp] = wm;
                spcnt[r*NW + warp] = (int)wcnt;
                spidx[r*NW + warp] = (int)widx;
            }
        }

        __syncthreads();                 // everyone done reading tiles[stage]
        int sn = s + DEPTH;
        if (t == 0 && sn * RPS < nrows) {
            mbar_expect_tx(mb0 + 8*stage, STAGEB);
            bulk_ldg(sbase + stage*STAGEB, (const char*)conf + (grow0 + sn*RPS) * ROWB, STAGEB, mb0 + 8*stage);
        }
        if (++stage == DEPTH) { stage = 0; ph ^= 1; }
    }
    __syncthreads();

    // combine 16 warp-partials per row
    if (t < nrows) {
        float m = -1.f; int c = 0, ix = 0;
#pragma unroll
        for (int w = 0; w < NW; w++) {
            float om = spmax[t*NW + w];
            if (om > m)       { m = om; c = spcnt[t*NW + w]; ix = spidx[t*NW + w]; }
            else if (om == m) { c += spcnt[t*NW + w]; ix = min(ix, spidx[t*NW + w]); }
        }
        size_t gi = grow0 + t;
        g_rowmax[gi] = m; g_rowj[gi] = ix; g_rowcnt[gi] = c;
    }

    // flush column-max partials (fire-and-forget RED.MAX)
    {
        unsigned* cm = &g_colmax[n * SS + 4*t];
        atomicMax(cm+0, c0.x); atomicMax(cm+1, c0.y); atomicMax(cm+2, c0.z); atomicMax(cm+3, c0.w);
        cm += 4*TPB;
        atomicMax(cm+0, c1.x); atomicMax(cm+1, c1.y); atomicMax(cm+2, c1.z); atomicMax(cm+3, c1.w);
        if (tail) {
            cm += 4*TPB;
            atomicMax(cm+0, c2.x); atomicMax(cm+1, c2.y); atomicMax(cm+2, c2.z); atomicMax(cm+3, c2.w);
        }
    }
}

__device__ __forceinline__ bool valid1(int j) {
    int r = j / W1, c = j % W1;
    return (r >= BR) & (r < H1 - BR) & (c >= BR) & (c < W1 - BR);
}

// thread-per-row fast path + CTA-cooperative rescan for the rare ambiguous rows
#define P2B 256
__global__ __launch_bounds__(P2B) void pass2(const float* __restrict__ conf,
                                             float* __restrict__ out) {
    __shared__ int   s_list[P2B];
    __shared__ float s_m[P2B];
    __shared__ int s_nl;
    __shared__ unsigned s_best;
    const int tid = threadIdx.x;
    const int gw  = blockIdx.x * P2B + tid;        // row id; grid exact: 75*256=19200
    if (tid == 0) s_nl = 0;
    __syncthreads();

    const int n = gw / LL, i = gw % LL;
    const float m  = g_rowmax[gw];
    const int cnt  = g_rowcnt[gw];
    const int jc   = g_rowj[gw];

    const int r0 = i / W0, c0 = i % W0;
    const bool v0 = (r0 >= BR) & (r0 < H0 - BR) & (c0 >= BR) & (c0 < W0 - BR);

    float mconf = 0.f; int jid = 0; float mv = 0.f;
    bool need = false;
    if (v0 && m > THRV) {
        // jc is the global min-index of the row max; if it passes the mask it is
        // the first True regardless of ties.
        if (valid1(jc) && g_colmax[n * SS + jc] == __float_as_uint(m)) {
            mv = 1.f; jid = jc; mconf = m;
        } else if (cnt > 1) {
            need = true;            // a later tied position may pass -> exact rescan
        }
    }
    if (need) { int p = atomicAdd(&s_nl, 1); s_list[p] = tid; s_m[tid] = m; }
    __syncthreads();
    if (!need) {
        out[gw]        = mconf;
        out[NL + gw]   = mv;
        out[2*NL + gw] = (float)jid;
    }

    const int nl = s_nl;
    for (int w = 0; w < nl; w++) {
        const int lrow = s_list[w];
        const int grow = blockIdx.x * P2B + lrow;
        const int nn = grow / LL, ii = grow % LL;
        const float mm = s_m[lrow];
        const float* rowp = conf + ((size_t)nn * LL + ii) * SS;
        if (tid == 0) s_best = 0x7fffffffu;
        __syncthreads();
        unsigned lb = 0x7fffffffu;
        for (int j = tid; j < SS; j += P2B) {
            float v = rowp[j];
            if (v == mm && valid1(j) && g_colmax[nn * SS + j] == __float_as_uint(v))
                lb = min(lb, (unsigned)j);
        }
        if (lb != 0x7fffffffu) atomicMin(&s_best, lb);
        __syncthreads();
        if (tid == 0) {
            unsigned b = s_best;
            bool hit = (b != 0x7fffffffu);
            out[grow]        = hit ? mm : 0.f;
            out[NL + grow]   = hit ? 1.f : 0.f;
            out[2*NL + grow] = hit ? (float)b : 0.f;
        }
        __syncthreads();
    }
}

extern "C" void kernel_launch(void* const* d_in, const int* in_sizes, int n_in,
                              void* d_out, int out_size) {
    const float* conf = (const float*)d_in[0];
    float* out = (float*)d_out;

    cudaFuncSetAttribute(pass1, cudaFuncAttributeMaxDynamicSharedMemorySize, SMEM_REQ);
    dim3 g1(CTAS_PER_N, NN);          // 37 x 4 = 148 CTAs = exactly 1 per SM
    pass1<<<g1, TPB, SMEM_REQ>>>(conf);
    pass2<<<NL / P2B, P2B>>>(conf, out);          // 75 CTAs
    cleanup_kernel<<<(NN*SS + 255)/256, 256>>>();
}